// round 14
// baseline (speedup 1.0000x reference)
#include <cuda_runtime.h>

// RNNModel: x[8192,512,8] fp32 -> out[8192] fp32.
// R13: 8 lanes per batch element -> 65536 threads / 2048 warps (3.46/SMSP).
// Lane owns 2 hidden channels as ONE packed b64; j-packed FMA2 everywhere;
// h exchange = 7 b64 shfl_xor; x loads cooperative/coalesced (128B per
// 8-lane group), redistributed via width-8 broadcasts. Weights pre-scaled
// by 2*log2(e); tanh = 1 - 2/(ex2(a)+1).

constexpr int T_LEN = 512;
constexpr int I_LEN = 8;
constexpr int H_LEN = 16;
constexpr int CHUNK = 8;                   // steps per buffer
constexpr int NCHUNK = T_LEN / CHUNK;      // 64
constexpr int LPC = 2 * CHUNK / 8;         // 16B pieces per lane per chunk (2)

typedef unsigned long long ull;

__device__ __forceinline__ ull ffma2(ull a, ull b, ull c) {
    ull d;
    asm("fma.rn.f32x2 %0, %1, %2, %3;" : "=l"(d) : "l"(a), "l"(b), "l"(c));
    return d;
}
__device__ __forceinline__ ull fmul2(ull a, ull b) {
    ull d;
    asm("mul.rn.f32x2 %0, %1, %2;" : "=l"(d) : "l"(a), "l"(b));
    return d;
}
__device__ __forceinline__ ull fadd2(ull a, ull b) {
    ull d;
    asm("add.rn.f32x2 %0, %1, %2;" : "=l"(d) : "l"(a), "l"(b));
    return d;
}
__device__ __forceinline__ ull pack2(float x, float y) {
    ull d;
    asm("mov.b64 %0, {%1, %2};" : "=l"(d) : "f"(x), "f"(y));
    return d;
}
__device__ __forceinline__ void unpack2(ull d, float& x, float& y) {
    asm("mov.b64 {%0, %1}, %2;" : "=f"(x), "=f"(y) : "l"(d));
}

// v pre-scaled by 2*log2(e): tanh = 1 - 2/(ex2(v)+1). ~1e-7 abs err.
__device__ __forceinline__ float tanh_pre(float v) {
    float e, r;
    asm("ex2.approx.f32 %0, %1;" : "=f"(e) : "f"(v));
    asm("rcp.approx.f32 %0, %1;" : "=f"(r) : "f"(e + 1.0f));
    return fmaf(-2.0f, r, 1.0f);
}

__global__ void __launch_bounds__(128) rnn_fused13_kernel(
    const float* __restrict__ x,
    const float* __restrict__ W_ih,
    const float* __restrict__ W_hh,
    const float* __restrict__ b_ih,
    const float* __restrict__ b_hh,
    const float* __restrict__ fc_w,
    const float* __restrict__ fc_b,
    float* __restrict__ out,
    int n_batch)
{
    const int tid = blockIdx.x * blockDim.x + threadIdx.x;
    const int sub = tid & 7;          // lane within 8-lane group
    const int b   = tid >> 3;         // batch element
    if (b >= n_batch) return;
    const int c0 = 2 * sub;           // own output-channel base (2 channels)

    const float C = 2.8853900817779268f;  // 2*log2(e) folded into weights

    // w2[i][m]: packed W_hh pair (input channels of lane sub^m) for output
    // c0+i. m=0 own hp, m=1..7 remote hp via shfl_xor(m).
    ull w2[2][8];
#pragma unroll
    for (int i = 0; i < 2; i++) {
        const int row = (c0 + i) * H_LEN;
#pragma unroll
        for (int m = 0; m < 8; m++) {
            const int cb = 2 * (sub ^ m);
            w2[i][m] = pack2(C * W_hh[row + cb], C * W_hh[row + cb + 1]);
        }
    }
    // u2[i][ip]: packed W_ih pair (inputs 2ip, 2ip+1) for output c0+i.
    ull u2[2][4];
#pragma unroll
    for (int i = 0; i < 2; i++) {
        const int row = (c0 + i) * I_LEN;
#pragma unroll
        for (int ip = 0; ip < 4; ip++)
            u2[i][ip] = pack2(C * W_ih[row + 2 * ip], C * W_ih[row + 2 * ip + 1]);
    }
    // bias in slot .x only (slot .y adds 0 in the horizontal sum).
    ull bias2[2];
#pragma unroll
    for (int i = 0; i < 2; i++)
        bias2[i] = pack2(C * (b_ih[c0 + i] + b_hh[c0 + i]), 0.0f);

    ull hp = 0ull;   // own packed pair (h_{c0}, h_{c0+1})

    const ulonglong2* xb =
        reinterpret_cast<const ulonglong2*>(x + (size_t)b * T_LEN * I_LEN);

    // One step. buf[r] holds this lane's pieces 8r+sub of the current chunk.
    auto step = [&](const ulonglong2* buf, int s) {
        // -- broadcast this step's two 16B pieces from owner lanes --
        const int p0 = 2 * s, p1 = 2 * s + 1;
        const int r0 = p0 >> 3, o0 = p0 & 7;
        const int r1 = p1 >> 3, o1 = p1 & 7;
        ull xq0 = __shfl_sync(0xffffffffu, buf[r0].x, o0, 8);
        ull xq1 = __shfl_sync(0xffffffffu, buf[r0].y, o0, 8);
        ull xq2 = __shfl_sync(0xffffffffu, buf[r1].x, o1, 8);
        ull xq3 = __shfl_sync(0xffffffffu, buf[r1].y, o1, 8);

        // -- h exchange (critical path start): 7 packed shuffles --
        ull rp[7];
#pragma unroll
        for (int m = 1; m < 8; m++)
            rp[m - 1] = __shfl_xor_sync(0xffffffffu, hp, m);

        // -- input projection (independent filler) --
        const ull xq[4] = {xq0, xq1, xq2, xq3};
        ull pa[2] = {bias2[0], bias2[1]};
#pragma unroll
        for (int ip = 0; ip < 4; ip++)
#pragma unroll
            for (int i = 0; i < 2; i++)
                pa[i] = ffma2(xq[ip], u2[i][ip], pa[i]);

        // -- recurrence: own pair first, then the 7 remote pairs --
        ull ra[2];
#pragma unroll
        for (int i = 0; i < 2; i++) ra[i] = fmul2(hp, w2[i][0]);
#pragma unroll
        for (int m = 1; m < 8; m++)
#pragma unroll
            for (int i = 0; i < 2; i++)
                ra[i] = ffma2(rp[m - 1], w2[i][m], ra[i]);

        // -- combine, horizontal add, tanh --
        float sx, sy, t0, t1;
        unpack2(fadd2(pa[0], ra[0]), sx, sy); t0 = tanh_pre(sx + sy);
        unpack2(fadd2(pa[1], ra[1]), sx, sy); t1 = tanh_pre(sx + sy);
        hp = pack2(t0, t1);
    };

    // Double-buffered chunks; chunk c = pieces [16c, 16c+16), lane takes
    // 16c + 8r + sub (128B contiguous per 8-lane group per r).
    ulonglong2 A[LPC], B[LPC];
#pragma unroll
    for (int r = 0; r < LPC; r++) A[r] = xb[8 * r + sub];

    for (int c = 0; c < NCHUNK; c += 2) {
        const int baseB = 2 * CHUNK * (c + 1);
#pragma unroll
        for (int r = 0; r < LPC; r++) B[r] = xb[baseB + 8 * r + sub];
#pragma unroll
        for (int s = 0; s < CHUNK; s++) step(A, s);

        if (c + 2 < NCHUNK) {
            const int baseA = 2 * CHUNK * (c + 2);
#pragma unroll
            for (int r = 0; r < LPC; r++) A[r] = xb[baseA + 8 * r + sub];
        }
#pragma unroll
        for (int s = 0; s < CHUNK; s++) step(B, s);
    }

    // fc over own 2 channels, butterfly-reduce across the 8-lane group.
    float h0, h1;
    unpack2(hp, h0, h1);
    float part = h0 * fc_w[c0] + h1 * fc_w[c0 + 1];
    part += __shfl_xor_sync(0xffffffffu, part, 1);
    part += __shfl_xor_sync(0xffffffffu, part, 2);
    part += __shfl_xor_sync(0xffffffffu, part, 4);
    if (sub == 0) out[b] = part + fc_b[0];
}

extern "C" void kernel_launch(void* const* d_in, const int* in_sizes, int n_in,
                              void* d_out, int out_size)
{
    const float* x    = (const float*)d_in[0];
    const float* W_ih = (const float*)d_in[1];
    const float* W_hh = (const float*)d_in[2];
    const float* b_ih = (const float*)d_in[3];
    const float* b_hh = (const float*)d_in[4];
    const float* fc_w = (const float*)d_in[5];
    const float* fc_b = (const float*)d_in[6];
    float* out = (float*)d_out;

    const int n_batch = out_size;        // 8192
    const int threads = n_batch * 8;     // 65536 (2048 warps)
    const int block   = 128;
    const int grid    = (threads + block - 1) / block;   // 512
    rnn_fused13_kernel<<<grid, block>>>(x, W_ih, W_hh, b_ih, b_hh, fc_w, fc_b,
                                        out, n_batch);
}